// round 4
// baseline (speedup 1.0000x reference)
#include <cuda_runtime.h>

// AverageSpanExtractor: out[b,n,:] = mean(seq[b, start:end, :]) * mask[b,n]
// seq:   [B,S,D] float32   (d_in[0])
// spans: [B,N,2] int32     (d_in[1])  (start, exclusive end)
// mask:  [B,N]   int32     (d_in[2])
// out:   [B,N,D] float32
//
// Span-persistent: grid of 1776 CTAs (one resident wave), each grid-strides
// over spans. Metadata for the next span is prefetched before the current
// span's row-gather loop so its latency hides behind the float4 burst.

#define MAX_W 20

__global__ __launch_bounds__(128, 12)
void avg_span_kernel(const float* __restrict__ seq,
                     const int* __restrict__ spans,
                     const int* __restrict__ mask,
                     float* __restrict__ out,
                     int S, int D, int N, int total)
{
    const int t = threadIdx.x;          // 0..127, owns float4 column t
    const int d4 = D >> 2;              // 128 float4 per row
    const int stride = gridDim.x;
    const long long bstride = (long long)S * d4;   // float4s per batch

    int sp = blockIdx.x;
    if (sp >= total) return;

    // prologue: load first span's metadata
    int s_cur = spans[2 * sp];
    int e_cur = spans[2 * sp + 1];
    int m_cur = mask[sp];

    while (true) {
        const int sp_next = sp + stride;
        // prefetch next span's metadata (hides behind the row gather below)
        int s_nxt = 0, e_nxt = 0, m_nxt = 0;
        const bool have_next = (sp_next < total);
        if (have_next) {
            s_nxt = spans[2 * sp_next];
            e_nxt = spans[2 * sp_next + 1];
            m_nxt = mask[sp_next];
        }

        int cnt = e_cur - s_cur;                 // width in [1, 20]
        cnt = (cnt < MAX_W) ? cnt : MAX_W;       // reference's static clamp
        cnt = (cnt > 0) ? cnt : 1;

        const int b = sp / N;                    // batch of this span
        const float4* __restrict__ p =
            (const float4*)seq + b * bstride + (long long)s_cur * d4 + t;

        float4 acc = make_float4(0.f, 0.f, 0.f, 0.f);
        #pragma unroll 4
        for (int i = 0; i < cnt; ++i) {
            float4 v = *p;
            p += d4;
            acc.x += v.x; acc.y += v.y; acc.z += v.z; acc.w += v.w;
        }

        const float scale = (float)m_cur / (float)cnt;
        acc.x *= scale; acc.y *= scale; acc.z *= scale; acc.w *= scale;

        float4* out4 = (float4*)out + (long long)sp * d4;
        out4[t] = acc;

        if (!have_next) break;
        sp = sp_next;
        s_cur = s_nxt; e_cur = e_nxt; m_cur = m_nxt;
    }
}

extern "C" void kernel_launch(void* const* d_in, const int* in_sizes, int n_in,
                              void* d_out, int out_size)
{
    const float* seq  = (const float*)d_in[0];
    const int* spans  = (const int*)d_in[1];
    const int* mask   = (const int*)d_in[2];
    float* out        = (float*)d_out;

    const int D = 512;
    const int S = 2048;
    const int B = in_sizes[0] / (S * D);         // 8
    const int N = in_sizes[2] / B;               // 1024
    const int total = B * N;                     // 8192 spans

    const int grid = 148 * 12;                   // one fully-resident wave
    dim3 block(D / 4);                           // 128 threads
    avg_span_kernel<<<grid, block>>>(seq, spans, mask, out, S, D, N, total);
}

// round 5
// speedup vs baseline: 1.0019x; 1.0019x over previous
#include <cuda_runtime.h>

// AverageSpanExtractor: out[b,n,:] = mean(seq[b, start:end, :]) * mask[b,n]
// seq:   [B,S,D] float32   (d_in[0])
// spans: [B,N,2] int32     (d_in[1])  (start, exclusive end)
// mask:  [B,N]   int32     (d_in[2])
// out:   [B,N,D] float32
//
// CTA per span (8192 CTAs, 128 threads). Span rows are contiguous in memory,
// so the block reads one linear cnt*2KB chunk, fully coalesced: thread t owns
// float4 column t of every row. 16 CTAs/SM (<=32 regs) for max latency hiding.

#define MAX_W 20

__global__ __launch_bounds__(128, 16)
void avg_span_kernel(const float* __restrict__ seq,
                     const int* __restrict__ spans,
                     const int* __restrict__ mask,
                     float* __restrict__ out,
                     int S, int D, int N)
{
    const int n = blockIdx.x;           // span index
    const int b = blockIdx.y;           // batch index
    const int t = threadIdx.x;          // 0..127, owns float4 column t

    const int sp = b * N + n;
    const int start = spans[2 * sp];
    const int end_e = spans[2 * sp + 1];        // exclusive end
    int cnt = end_e - start;                    // width in [1, 20]
    cnt = (cnt < MAX_W) ? cnt : MAX_W;          // reference's static clamp
    cnt = (cnt > 0) ? cnt : 1;

    const int d4 = D >> 2;                      // 128 float4 per row
    const float4* __restrict__ p =
        (const float4*)(seq + (long long)b * S * D) + (long long)start * d4 + t;

    float4 acc = make_float4(0.f, 0.f, 0.f, 0.f);

    // uniform per-block trip count; pointer-increment addressing
    #pragma unroll 4
    for (int i = 0; i < cnt; ++i) {
        float4 v = *p;
        p += d4;
        acc.x += v.x; acc.y += v.y; acc.z += v.z; acc.w += v.w;
    }

    const float scale = (float)mask[sp] / (float)cnt;
    acc.x *= scale; acc.y *= scale; acc.z *= scale; acc.w *= scale;

    float4* out4 = (float4*)(out + (long long)sp * D);
    out4[t] = acc;
}

extern "C" void kernel_launch(void* const* d_in, const int* in_sizes, int n_in,
                              void* d_out, int out_size)
{
    const float* seq  = (const float*)d_in[0];
    const int* spans  = (const int*)d_in[1];
    const int* mask   = (const int*)d_in[2];
    float* out        = (float*)d_out;

    const int D = 512;
    const int S = 2048;
    const int B = in_sizes[0] / (S * D);         // 8
    const int N = in_sizes[2] / B;               // 1024

    dim3 grid(N, B);
    dim3 block(D / 4);                           // 128 threads
    avg_span_kernel<<<grid, block>>>(seq, spans, mask, out, S, D, N);
}